// round 13
// baseline (speedup 1.0000x reference)
#include <cuda_runtime.h>
#include <math.h>

#define BB 2
#define LL 256
#define NH 8
#define DQ 64
#define DM 512

// ---------------- scratch (no allocation allowed) ----------------
__device__ float  g_q[BB*NH*LL*DQ];
__device__ float  g_k[BB*NH*LL*DQ];
__device__ float  g_v[BB*NH*LL*DQ];
__device__ float  g_attn[BB*NH*LL*LL];        // raw logits (softmax fused into rnn)
__device__ float2 g_u[BB*NH*LL*DQ + 512];     // +pad for prefetch overrun
__device__ float  g_rnn[BB*LL*DM];
__device__ float  g_part[4][BB*LL*DM];        // split-K partials for out gemm

// ================= double-buffered GEMM body (64x64 tile, 4x4 microtile) =================
struct GemmAcc { float v[4][4]; };

__device__ __forceinline__ void gemm_core_ks(
    const float* __restrict__ X, const float* __restrict__ W,
    float As[2][16][64], float Bs[2][16][64],
    int row0, int col0, int k_base, int nstage, int tid, GemmAcc& acc)
{
    const int tx = tid & 15, ty = tid >> 4;
    const int m  = tid >> 2,  kk = (tid & 3) * 4;
    const int kr = tid >> 4,  nn = (tid & 15) * 4;

    {
        float4 av = *(const float4*)&X[(row0 + m) * 512 + k_base + kk];
        As[0][kk+0][m] = av.x; As[0][kk+1][m] = av.y; As[0][kk+2][m] = av.z; As[0][kk+3][m] = av.w;
        *(float4*)&Bs[0][kr][nn] = *(const float4*)&W[(k_base + kr) * 512 + col0 + nn];
    }
    __syncthreads();

    for (int s = 0; s < nstage; ++s) {
        const int cur = s & 1;
        float4 av, bv;
        if (s < nstage - 1) {
            const int k0 = k_base + (s + 1) * 16;
            av = *(const float4*)&X[(row0 + m) * 512 + k0 + kk];
            bv = *(const float4*)&W[(k0 + kr) * 512 + col0 + nn];
        }
        #pragma unroll
        for (int k = 0; k < 16; ++k) {
            float4 a4 = *(const float4*)&As[cur][k][ty * 4];
            float4 b4 = *(const float4*)&Bs[cur][k][tx * 4];
            float a[4] = {a4.x, a4.y, a4.z, a4.w};
            float b[4] = {b4.x, b4.y, b4.z, b4.w};
            #pragma unroll
            for (int i = 0; i < 4; ++i)
                #pragma unroll
                for (int j = 0; j < 4; ++j)
                    acc.v[i][j] = fmaf(a[i], b[j], acc.v[i][j]);
        }
        if (s < nstage - 1) {
            const int nxt = cur ^ 1;
            As[nxt][kk+0][m] = av.x; As[nxt][kk+1][m] = av.y;
            As[nxt][kk+2][m] = av.z; As[nxt][kk+3][m] = av.w;
            *(float4*)&Bs[nxt][kr][nn] = bv;
        }
        __syncthreads();
    }
}

// ================= fused QKV GEMM (z selects projection), remapped write =================
__global__ __launch_bounds__(256) void qkv_gemm(
    const float* __restrict__ xq, const float* __restrict__ xk, const float* __restrict__ xv,
    const float* __restrict__ Wq, const float* __restrict__ Wk, const float* __restrict__ Wv,
    const float* __restrict__ bq, const float* __restrict__ bk, const float* __restrict__ bv)
{
    __shared__ float As[2][16][64];
    __shared__ float Bs[2][16][64];
    const int z = blockIdx.z;
    const float* X    = (z == 0) ? xq : (z == 1) ? xk : xv;
    const float* W    = (z == 0) ? Wq : (z == 1) ? Wk : Wv;
    const float* bias = (z == 0) ? bq : (z == 1) ? bk : bv;
    float* Out        = (z == 0) ? g_q : (z == 1) ? g_k : g_v;

    const int tid = threadIdx.x;
    const int tx = tid & 15, ty = tid >> 4;
    const int row0 = blockIdx.x * 64, col0 = blockIdx.y * 64;
    GemmAcc acc = {};
    gemm_core_ks(X, W, As, Bs, row0, col0, 0, 32, tid, acc);

    #pragma unroll
    for (int i = 0; i < 4; ++i) {
        int mm = row0 + ty * 4 + i;
        #pragma unroll
        for (int j = 0; j < 4; ++j) {
            int n = col0 + tx * 4 + j;
            float val = acc.v[i][j] + bias[n];
            int b = mm >> 8, l = mm & 255, h = n >> 6, d = n & 63;
            Out[(((b * NH + h) << 8) + l) * DQ + d] = val;
        }
    }
}

// ================= out GEMM split-K=4: partial[z] over k in [z*128,(z+1)*128) =================
__global__ __launch_bounds__(256) void out_gemm_splitk(const float* __restrict__ W)
{
    __shared__ float As[2][16][64];
    __shared__ float Bs[2][16][64];
    const int tid = threadIdx.x;
    const int tx = tid & 15, ty = tid >> 4;
    const int row0 = blockIdx.x * 64, col0 = blockIdx.y * 64;
    const int z = blockIdx.z;
    GemmAcc acc = {};
    gemm_core_ks(g_rnn, W, As, Bs, row0, col0, z * 128, 8, tid, acc);

    float* dst = g_part[z];
    #pragma unroll
    for (int i = 0; i < 4; ++i) {
        int mm = row0 + ty * 4 + i;
        #pragma unroll
        for (int j = 0; j < 4; ++j) {
            int n = col0 + tx * 4 + j;
            dst[mm * 512 + n] = acc.v[i][j];
        }
    }
}

// ================= reduce: out = sum(part) + bias =================
__global__ __launch_bounds__(256) void out_reduce(
    const float* __restrict__ bias, float* __restrict__ Out)
{
    const int gidx = blockIdx.x * 256 + threadIdx.x;   // float4 index, 0..65535
    float4 p0 = ((const float4*)g_part[0])[gidx];
    float4 p1 = ((const float4*)g_part[1])[gidx];
    float4 p2 = ((const float4*)g_part[2])[gidx];
    float4 p3 = ((const float4*)g_part[3])[gidx];
    float4 b4 = ((const float4*)bias)[gidx & 127];
    float4 r;
    r.x = (p0.x + p1.x) + (p2.x + p3.x) + b4.x;
    r.y = (p0.y + p1.y) + (p2.y + p3.y) + b4.y;
    r.z = (p0.z + p1.z) + (p2.z + p3.z) + b4.z;
    r.w = (p0.w + p1.w) + (p2.w + p3.w) + b4.w;
    ((float4*)Out)[gidx] = r;
}

// ================= merged logits + u kernel =================
__global__ __launch_bounds__(256) void mid_kernel(
    const float* __restrict__ mask,
    const float* __restrict__ Wre, const float* __restrict__ Wim)
{
    __shared__ float sh[10240];
    const int bid = blockIdx.x;
    const int tid = threadIdx.x;

    if (bid < 256) {
        float* Qs = sh;
        float* Ks = sh + 64 * 65;
        const int q0 = (bid & 3) * 64, t0 = ((bid >> 2) & 3) * 64, bh = bid >> 4;
        const int b = bh >> 3;
        {
            const float* qsrc = &g_q[(bh * LL + q0) * DQ];
            const float* ksrc = &g_k[(bh * LL + t0) * DQ];
            #pragma unroll
            for (int i = 0; i < 4; ++i) {
                int idx = tid + 256 * i;
                int r = idx >> 4;
                int c = (idx & 15) * 4;
                float4 v = *(const float4*)&qsrc[r * 64 + c];
                Qs[r*65+c] = v.x; Qs[r*65+c+1] = v.y; Qs[r*65+c+2] = v.z; Qs[r*65+c+3] = v.w;
                float4 w = *(const float4*)&ksrc[r * 64 + c];
                Ks[r*65+c] = w.x; Ks[r*65+c+1] = w.y; Ks[r*65+c+2] = w.z; Ks[r*65+c+3] = w.w;
            }
        }
        __syncthreads();
        const int tx = tid & 15, ty = tid >> 4;
        float acc[4][4] = {};
        #pragma unroll 8
        for (int d = 0; d < 64; ++d) {
            float a[4], bb[4];
            #pragma unroll
            for (int i = 0; i < 4; ++i) a[i]  = Qs[(ty * 4 + i)*65 + d];
            #pragma unroll
            for (int j = 0; j < 4; ++j) bb[j] = Ks[(tx * 4 + j)*65 + d];
            #pragma unroll
            for (int i = 0; i < 4; ++i)
                #pragma unroll
                for (int j = 0; j < 4; ++j)
                    acc[i][j] = fmaf(a[i], bb[j], acc[i][j]);
        }
        const float NEG_INF = -__int_as_float(0x7f800000);
        #pragma unroll
        for (int i = 0; i < 4; ++i) {
            int q = q0 + ty * 4 + i;
            #pragma unroll
            for (int j = 0; j < 4; ++j) {
                int t = t0 + tx * 4 + j;
                float v = acc[i][j] * 0.125f;
                float mval = mask[b * LL * LL + q * LL + t];
                v = (mval == 1.0f) ? NEG_INF : v - mval;
                g_attn[(bh * LL + q) * LL + t] = v;
            }
        }
    } else {
        float* Vs = sh;
        float* Wr = sh + 2048;
        float* Wi = sh + 6144;
        const int b2 = bid - 256;
        const int bh = b2 & 15;
        const int rb = b2 >> 4;
        const int h  = bh & 7;
        {
            const float4* vsrc = (const float4*)&g_v[(bh * LL + rb * 32) * DQ];
            float4* vdst = (float4*)Vs;
            vdst[tid]       = vsrc[tid];
            vdst[tid + 256] = vsrc[tid + 256];
            const float4* wr = (const float4*)&Wre[h * 4096];
            const float4* wi = (const float4*)&Wim[h * 4096];
            float4* wrd = (float4*)Wr;
            float4* wid = (float4*)Wi;
            #pragma unroll
            for (int i = 0; i < 4; ++i) {
                wrd[tid + 256 * i] = wr[tid + 256 * i];
                wid[tid + 256 * i] = wi[tid + 256 * i];
            }
        }
        __syncthreads();
        const int tx = tid & 15, ty = tid >> 4;
        float ar[2][4] = {}, ai[2][4] = {};
        #pragma unroll 8
        for (int d = 0; d < 64; ++d) {
            float a0 = Vs[(ty * 2 + 0)*64 + d];
            float a1 = Vs[(ty * 2 + 1)*64 + d];
            float4 wr4 = *(const float4*)&Wr[d*64 + tx * 4];
            float4 wi4 = *(const float4*)&Wi[d*64 + tx * 4];
            float wrv[4] = {wr4.x, wr4.y, wr4.z, wr4.w};
            float wiv[4] = {wi4.x, wi4.y, wi4.z, wi4.w};
            #pragma unroll
            for (int j = 0; j < 4; ++j) {
                ar[0][j] = fmaf(a0, wrv[j], ar[0][j]);
                ai[0][j] = fmaf(a0, wiv[j], ai[0][j]);
                ar[1][j] = fmaf(a1, wrv[j], ar[1][j]);
                ai[1][j] = fmaf(a1, wiv[j], ai[1][j]);
            }
        }
        #pragma unroll
        for (int i = 0; i < 2; ++i) {
            int t = rb * 32 + ty * 2 + i;
            #pragma unroll
            for (int j = 0; j < 4; ++j) {
                int e = tx * 4 + j;
                g_u[(bh * LL + t) * DQ + e] = make_float2(ar[i][j], ai[i][j]);
            }
        }
    }
}

// ================= fused softmax + EUNN scan: one warp per (b,h,q) chain =================
__global__ __launch_bounds__(256, 4) void rnn_kernel(
    const float* __restrict__ theta, const float* __restrict__ phi,
    const float* __restrict__ rbias, float* __restrict__ attn_out)
{
    const int w = (blockIdx.x * blockDim.x + threadIdx.x) >> 5;  // 0..4095
    const int lane = threadIdx.x & 31;
    const int bh = w >> 8;
    const int q  = w & 255;
    const int h  = bh & 7;
    const unsigned FULL = 0xffffffffu;

    // ---- rotation coefficients: combined products (A = s*cosphi, B = s*sinphi) ----
    float c0, s0, cp0, sp0, c1, s1, cp1, sp1;
    sincosf(theta[(h * 2 + 0) * 32 + lane], &s0, &c0);
    sincosf(theta[(h * 2 + 1) * 32 + lane], &s1, &c1);
    sincosf(phi[(h * 2 + 0) * 32 + lane], &sp0, &cp0);
    sincosf(phi[(h * 2 + 1) * 32 + lane], &sp1, &cp1);
    const float A0 = s0 * cp0, B0 = s0 * sp0;
    const float A1 = s1 * cp1, B1 = s1 * sp1;
    const int lm = (lane + 31) & 31;
    const int lp = (lane + 1) & 31;
    const float c1m = __shfl_sync(FULL, c1, lm);
    const float A1m = __shfl_sync(FULL, A1, lm);
    const float B1m = __shfl_sync(FULL, B1, lm);
    const float bb0 = rbias[h * 64 + 2 * lane];
    const float bb1 = rbias[h * 64 + 2 * lane + 1];

    // ---- in-register softmax of this row ----
    const float* row = &g_attn[(bh * LL + q) * LL];
    float x[8];
    float mx = -__int_as_float(0x7f800000);
    #pragma unroll
    for (int j = 0; j < 8; ++j) { x[j] = row[lane + 32 * j]; mx = fmaxf(mx, x[j]); }
    #pragma unroll
    for (int off = 16; off > 0; off >>= 1) mx = fmaxf(mx, __shfl_xor_sync(FULL, mx, off));
    float s = 0.0f;
    #pragma unroll
    for (int j = 0; j < 8; ++j) { x[j] = __expf(x[j] - mx); s += x[j]; }
    #pragma unroll
    for (int off = 16; off > 0; off >>= 1) s += __shfl_xor_sync(FULL, s, off);
    float inv = 1.0f / s;
    #pragma unroll
    for (int j = 0; j < 8; ++j) x[j] *= inv;
    if (attn_out) {
        float* ao = &attn_out[(bh * LL + q) * LL];
        #pragma unroll
        for (int j = 0; j < 8; ++j) ao[lane + 32 * j] = x[j];
    }

    // ---- sequential scan with depth-3 u prefetch ring ----
    const float4* ub_lane = (const float4*)&g_u[bh * LL * DQ] + lane;
    float4 ring[4];
    ring[0] = ub_lane[0];
    ring[1] = ub_lane[32];
    ring[2] = ub_lane[64];
    ring[3] = ub_lane[64];   // dummy; overwritten at t=0

    float h0r = 0.f, h0i = 0.f, h1r = 0.f, h1i = 0.f;

    for (int chunk = 0; chunk < 8; ++chunk) {
        float xa = x[chunk];
        #pragma unroll 4
        for (int tt = 0; tt < 32; ++tt) {
            const int t = chunk * 32 + tt;
            float a = __shfl_sync(FULL, xa, tt);
            // prefetch t+3 into slot (t+3)&3 (holds consumed t-1)
            ring[(tt + 3) & 3] = ub_lane[(t + 3) * 32];
            // --- layer 0: pair (2l, 2l+1), lane-local, scalar FMA tree ---
            {
                float nar = fmaf(c0, h0r, fmaf(-A0, h1r,  B0 * h1i));
                float nai = fmaf(c0, h0i, fmaf(-A0, h1i, -B0 * h1r));
                float nbr = fmaf(c0, h1r, fmaf( A0, h0r,  B0 * h0i));
                float nbi = fmaf(c0, h1i, fmaf( A0, h0i, -B0 * h0r));
                h0r = nar; h0i = nai; h1r = nbr; h1i = nbi;
            }
            // --- layer 1: parallel shuffles on layer-0 state ---
            {
                float h0pr = __shfl_sync(FULL, h0r, lp);
                float h0pi = __shfl_sync(FULL, h0i, lp);
                float h1mr = __shfl_sync(FULL, h1r, lm);
                float h1mi = __shfl_sync(FULL, h1i, lm);
                float nh1r = fmaf(c1, h1r, fmaf(-A1, h0pr,  B1 * h0pi));
                float nh1i = fmaf(c1, h1i, fmaf(-A1, h0pi, -B1 * h0pr));
                float nh0r = fmaf(c1m, h0r, fmaf(A1m, h1mr,  B1m * h1mi));
                float nh0i = fmaf(c1m, h0i, fmaf(A1m, h1mi, -B1m * h1mr));
                h0r = nh0r; h0i = nh0i; h1r = nh1r; h1i = nh1i;
            }
            // --- + a * u ---
            float4 u4 = ring[tt & 3];
            h0r = fmaf(a, u4.x, h0r); h0i = fmaf(a, u4.y, h0i);
            h1r = fmaf(a, u4.z, h1r); h1i = fmaf(a, u4.w, h1i);
            // --- modrelu (shared-rcp) ---
            {
                float m2_0 = fmaf(h0r, h0r, h0i * h0i);
                float m2_1 = fmaf(h1r, h1r, h1i * h1i);
                float rs0  = rsqrtf(fmaxf(m2_0, 1e-36f));
                float rs1  = rsqrtf(fmaxf(m2_1, 1e-36f));
                float m0   = m2_0 * rs0;
                float m1   = m2_1 * rs1;
                float n0   = fmaxf(m0 + bb0, 0.0f);
                float n1   = fmaxf(m1 + bb1, 0.0f);
                float d0   = m0 + 1e-5f;
                float d1   = m1 + 1e-5f;
                float rdd  = __fdividef(1.0f, d0 * d1);
                float sc0  = n0 * d1 * rdd;
                float sc1  = n1 * d0 * rdd;
                h0r *= sc0; h0i *= sc0;
                h1r *= sc1; h1i *= sc1;
            }
        }
    }
    const int b = bh >> 3;
    float* dst = &g_rnn[(b * LL + q) * DM + h * DQ];
    dst[2 * lane]     = h0r;
    dst[2 * lane + 1] = h1r;
}

// ---------------- launch ----------------
extern "C" void kernel_launch(void* const* d_in, const int* in_sizes, int n_in,
                              void* d_out, int out_size)
{
    const float* x_q    = (const float*)d_in[0];
    const float* x_k    = (const float*)d_in[1];
    const float* x_v    = (const float*)d_in[2];
    const float* maskp  = (const float*)d_in[3];
    const float* Wq     = (const float*)d_in[4];
    const float* bq     = (const float*)d_in[5];
    const float* Wk     = (const float*)d_in[6];
    const float* bk     = (const float*)d_in[7];
    const float* Wv     = (const float*)d_in[8];
    const float* bv     = (const float*)d_in[9];
    const float* Wo     = (const float*)d_in[10];
    const float* bo     = (const float*)d_in[11];
    const float* theta  = (const float*)d_in[12];
    const float* phi    = (const float*)d_in[13];
    const float* Win_re = (const float*)d_in[14];
    const float* Win_im = (const float*)d_in[15];
    const float* rbias  = (const float*)d_in[16];

    float* out = (float*)d_out;
    const int OUT_ELEMS  = BB * LL * DM;          // 262144
    const int ATTN_ELEMS = BB * NH * LL * LL;     // 1048576
    float* attn_out = (out_size >= OUT_ELEMS + ATTN_ELEMS) ? (out + OUT_ELEMS) : nullptr;

    qkv_gemm<<<dim3(8, 8, 3), 256>>>(x_q, x_k, x_v, Wq, Wk, Wv, bq, bk, bv);

    mid_kernel<<<384, 256>>>(maskp, Win_re, Win_im);

    rnn_kernel<<<512, 256>>>(theta, phi, rbias, attn_out);

    out_gemm_splitk<<<dim3(8, 8, 4), 256>>>(Wo);
    out_reduce<<<256, 256>>>(bo, out);
}

// round 15
// speedup vs baseline: 1.0042x; 1.0042x over previous
#include <cuda_runtime.h>
#include <math.h>

#define BB 2
#define LL 256
#define NH 8
#define DQ 64
#define DM 512

// ---------------- scratch (no allocation allowed) ----------------
__device__ float  g_q[BB*NH*LL*DQ];
__device__ float  g_k[BB*NH*LL*DQ];
__device__ float  g_v[BB*NH*LL*DQ];
__device__ float  g_attn[BB*NH*LL*LL];        // raw logits (softmax fused into rnn)
__device__ float2 g_u[BB*NH*LL*DQ + 512];     // +pad for prefetch overrun
__device__ float  g_rnn[BB*LL*DM];
__device__ float  g_part[4][BB*LL*DM];        // split-K partials for out gemm

// ---------------- f32x2 helpers ----------------
__device__ __forceinline__ unsigned long long pk2(float lo, float hi) {
    unsigned long long r;
    asm("mov.b64 %0, {%1, %2};" : "=l"(r) : "f"(lo), "f"(hi));
    return r;
}
// out = C (x) {hr,hi} + Am (x) {or_,oi} + Bp (x) {oi,or_}   (elementwise f32x2)
__device__ __forceinline__ void rot2(float& outr, float& outi,
    unsigned long long C, unsigned long long Am, unsigned long long Bp,
    float hr, float hi, float or_, float oi)
{
    asm("{\n\t"
        ".reg .b64 H, O, Os, T, R;\n\t"
        "mov.b64 H,  {%2, %3};\n\t"
        "mov.b64 O,  {%4, %5};\n\t"
        "mov.b64 Os, {%5, %4};\n\t"
        "mul.rn.f32x2 T, %8, Os;\n\t"
        "fma.rn.f32x2 T, %7, O, T;\n\t"
        "fma.rn.f32x2 R, %6, H, T;\n\t"
        "mov.b64 {%0, %1}, R;\n\t"
        "}" : "=f"(outr), "=f"(outi)
            : "f"(hr), "f"(hi), "f"(or_), "f"(oi),
              "l"(C), "l"(Am), "l"(Bp));
}

// ================= double-buffered GEMM body (64x64 tile, 4x4 microtile) =================
struct GemmAcc { float v[4][4]; };

__device__ __forceinline__ void gemm_core_ks(
    const float* __restrict__ X, const float* __restrict__ W,
    float As[2][16][64], float Bs[2][16][64],
    int row0, int col0, int k_base, int nstage, int tid, GemmAcc& acc)
{
    const int tx = tid & 15, ty = tid >> 4;
    const int m  = tid >> 2,  kk = (tid & 3) * 4;
    const int kr = tid >> 4,  nn = (tid & 15) * 4;

    {
        float4 av = *(const float4*)&X[(row0 + m) * 512 + k_base + kk];
        As[0][kk+0][m] = av.x; As[0][kk+1][m] = av.y; As[0][kk+2][m] = av.z; As[0][kk+3][m] = av.w;
        *(float4*)&Bs[0][kr][nn] = *(const float4*)&W[(k_base + kr) * 512 + col0 + nn];
    }
    __syncthreads();

    for (int s = 0; s < nstage; ++s) {
        const int cur = s & 1;
        float4 av, bv;
        if (s < nstage - 1) {
            const int k0 = k_base + (s + 1) * 16;
            av = *(const float4*)&X[(row0 + m) * 512 + k0 + kk];
            bv = *(const float4*)&W[(k0 + kr) * 512 + col0 + nn];
        }
        #pragma unroll
        for (int k = 0; k < 16; ++k) {
            float4 a4 = *(const float4*)&As[cur][k][ty * 4];
            float4 b4 = *(const float4*)&Bs[cur][k][tx * 4];
            float a[4] = {a4.x, a4.y, a4.z, a4.w};
            float b[4] = {b4.x, b4.y, b4.z, b4.w};
            #pragma unroll
            for (int i = 0; i < 4; ++i)
                #pragma unroll
                for (int j = 0; j < 4; ++j)
                    acc.v[i][j] = fmaf(a[i], b[j], acc.v[i][j]);
        }
        if (s < nstage - 1) {
            const int nxt = cur ^ 1;
            As[nxt][kk+0][m] = av.x; As[nxt][kk+1][m] = av.y;
            As[nxt][kk+2][m] = av.z; As[nxt][kk+3][m] = av.w;
            *(float4*)&Bs[nxt][kr][nn] = bv;
        }
        __syncthreads();
    }
}

// ================= fused QKV GEMM (z selects projection), remapped write =================
__global__ __launch_bounds__(256) void qkv_gemm(
    const float* __restrict__ xq, const float* __restrict__ xk, const float* __restrict__ xv,
    const float* __restrict__ Wq, const float* __restrict__ Wk, const float* __restrict__ Wv,
    const float* __restrict__ bq, const float* __restrict__ bk, const float* __restrict__ bv)
{
    __shared__ float As[2][16][64];
    __shared__ float Bs[2][16][64];
    const int z = blockIdx.z;
    const float* X    = (z == 0) ? xq : (z == 1) ? xk : xv;
    const float* W    = (z == 0) ? Wq : (z == 1) ? Wk : Wv;
    const float* bias = (z == 0) ? bq : (z == 1) ? bk : bv;
    float* Out        = (z == 0) ? g_q : (z == 1) ? g_k : g_v;

    const int tid = threadIdx.x;
    const int tx = tid & 15, ty = tid >> 4;
    const int row0 = blockIdx.x * 64, col0 = blockIdx.y * 64;
    GemmAcc acc = {};
    gemm_core_ks(X, W, As, Bs, row0, col0, 0, 32, tid, acc);

    #pragma unroll
    for (int i = 0; i < 4; ++i) {
        int mm = row0 + ty * 4 + i;
        #pragma unroll
        for (int j = 0; j < 4; ++j) {
            int n = col0 + tx * 4 + j;
            float val = acc.v[i][j] + bias[n];
            int b = mm >> 8, l = mm & 255, h = n >> 6, d = n & 63;
            Out[(((b * NH + h) << 8) + l) * DQ + d] = val;
        }
    }
}

// ================= out GEMM split-K=4: partial[z] over k in [z*128,(z+1)*128) =================
__global__ __launch_bounds__(256) void out_gemm_splitk(const float* __restrict__ W)
{
    __shared__ float As[2][16][64];
    __shared__ float Bs[2][16][64];
    const int tid = threadIdx.x;
    const int tx = tid & 15, ty = tid >> 4;
    const int row0 = blockIdx.x * 64, col0 = blockIdx.y * 64;
    const int z = blockIdx.z;
    GemmAcc acc = {};
    gemm_core_ks(g_rnn, W, As, Bs, row0, col0, z * 128, 8, tid, acc);

    float* dst = g_part[z];
    #pragma unroll
    for (int i = 0; i < 4; ++i) {
        int mm = row0 + ty * 4 + i;
        #pragma unroll
        for (int j = 0; j < 4; ++j) {
            int n = col0 + tx * 4 + j;
            dst[mm * 512 + n] = acc.v[i][j];
        }
    }
}

// ================= reduce: out = sum(part) + bias =================
__global__ __launch_bounds__(256) void out_reduce(
    const float* __restrict__ bias, float* __restrict__ Out)
{
    const int gidx = blockIdx.x * 256 + threadIdx.x;   // float4 index, 0..65535
    float4 p0 = ((const float4*)g_part[0])[gidx];
    float4 p1 = ((const float4*)g_part[1])[gidx];
    float4 p2 = ((const float4*)g_part[2])[gidx];
    float4 p3 = ((const float4*)g_part[3])[gidx];
    float4 b4 = ((const float4*)bias)[gidx & 127];
    float4 r;
    r.x = (p0.x + p1.x) + (p2.x + p3.x) + b4.x;
    r.y = (p0.y + p1.y) + (p2.y + p3.y) + b4.y;
    r.z = (p0.z + p1.z) + (p2.z + p3.z) + b4.z;
    r.w = (p0.w + p1.w) + (p2.w + p3.w) + b4.w;
    ((float4*)Out)[gidx] = r;
}

// ================= merged logits + u kernel =================
__global__ __launch_bounds__(256) void mid_kernel(
    const float* __restrict__ mask,
    const float* __restrict__ Wre, const float* __restrict__ Wim)
{
    __shared__ float sh[10240];
    const int bid = blockIdx.x;
    const int tid = threadIdx.x;

    if (bid < 256) {
        float* Qs = sh;
        float* Ks = sh + 64 * 65;
        const int q0 = (bid & 3) * 64, t0 = ((bid >> 2) & 3) * 64, bh = bid >> 4;
        const int b = bh >> 3;
        {
            const float* qsrc = &g_q[(bh * LL + q0) * DQ];
            const float* ksrc = &g_k[(bh * LL + t0) * DQ];
            #pragma unroll
            for (int i = 0; i < 4; ++i) {
                int idx = tid + 256 * i;
                int r = idx >> 4;
                int c = (idx & 15) * 4;
                float4 v = *(const float4*)&qsrc[r * 64 + c];
                Qs[r*65+c] = v.x; Qs[r*65+c+1] = v.y; Qs[r*65+c+2] = v.z; Qs[r*65+c+3] = v.w;
                float4 w = *(const float4*)&ksrc[r * 64 + c];
                Ks[r*65+c] = w.x; Ks[r*65+c+1] = w.y; Ks[r*65+c+2] = w.z; Ks[r*65+c+3] = w.w;
            }
        }
        __syncthreads();
        const int tx = tid & 15, ty = tid >> 4;
        float acc[4][4] = {};
        #pragma unroll 8
        for (int d = 0; d < 64; ++d) {
            float a[4], bb[4];
            #pragma unroll
            for (int i = 0; i < 4; ++i) a[i]  = Qs[(ty * 4 + i)*65 + d];
            #pragma unroll
            for (int j = 0; j < 4; ++j) bb[j] = Ks[(tx * 4 + j)*65 + d];
            #pragma unroll
            for (int i = 0; i < 4; ++i)
                #pragma unroll
                for (int j = 0; j < 4; ++j)
                    acc[i][j] = fmaf(a[i], bb[j], acc[i][j]);
        }
        const float NEG_INF = -__int_as_float(0x7f800000);
        #pragma unroll
        for (int i = 0; i < 4; ++i) {
            int q = q0 + ty * 4 + i;
            #pragma unroll
            for (int j = 0; j < 4; ++j) {
                int t = t0 + tx * 4 + j;
                float v = acc[i][j] * 0.125f;
                float mval = mask[b * LL * LL + q * LL + t];
                v = (mval == 1.0f) ? NEG_INF : v - mval;
                g_attn[(bh * LL + q) * LL + t] = v;
            }
        }
    } else {
        float* Vs = sh;
        float* Wr = sh + 2048;
        float* Wi = sh + 6144;
        const int b2 = bid - 256;
        const int bh = b2 & 15;
        const int rb = b2 >> 4;
        const int h  = bh & 7;
        {
            const float4* vsrc = (const float4*)&g_v[(bh * LL + rb * 32) * DQ];
            float4* vdst = (float4*)Vs;
            vdst[tid]       = vsrc[tid];
            vdst[tid + 256] = vsrc[tid + 256];
            const float4* wr = (const float4*)&Wre[h * 4096];
            const float4* wi = (const float4*)&Wim[h * 4096];
            float4* wrd = (float4*)Wr;
            float4* wid = (float4*)Wi;
            #pragma unroll
            for (int i = 0; i < 4; ++i) {
                wrd[tid + 256 * i] = wr[tid + 256 * i];
                wid[tid + 256 * i] = wi[tid + 256 * i];
            }
        }
        __syncthreads();
        const int tx = tid & 15, ty = tid >> 4;
        float ar[2][4] = {}, ai[2][4] = {};
        #pragma unroll 8
        for (int d = 0; d < 64; ++d) {
            float a0 = Vs[(ty * 2 + 0)*64 + d];
            float a1 = Vs[(ty * 2 + 1)*64 + d];
            float4 wr4 = *(const float4*)&Wr[d*64 + tx * 4];
            float4 wi4 = *(const float4*)&Wi[d*64 + tx * 4];
            float wrv[4] = {wr4.x, wr4.y, wr4.z, wr4.w};
            float wiv[4] = {wi4.x, wi4.y, wi4.z, wi4.w};
            #pragma unroll
            for (int j = 0; j < 4; ++j) {
                ar[0][j] = fmaf(a0, wrv[j], ar[0][j]);
                ai[0][j] = fmaf(a0, wiv[j], ai[0][j]);
                ar[1][j] = fmaf(a1, wrv[j], ar[1][j]);
                ai[1][j] = fmaf(a1, wiv[j], ai[1][j]);
            }
        }
        #pragma unroll
        for (int i = 0; i < 2; ++i) {
            int t = rb * 32 + ty * 2 + i;
            #pragma unroll
            for (int j = 0; j < 4; ++j) {
                int e = tx * 4 + j;
                g_u[(bh * LL + t) * DQ + e] = make_float2(ar[i][j], ai[i][j]);
            }
        }
    }
}

// ================= fused softmax + EUNN scan: one warp per (b,h,q) chain =================
__global__ __launch_bounds__(256, 4) void rnn_kernel(
    const float* __restrict__ theta, const float* __restrict__ phi,
    const float* __restrict__ rbias, float* __restrict__ attn_out)
{
    const int w = (blockIdx.x * blockDim.x + threadIdx.x) >> 5;  // 0..4095
    const int lane = threadIdx.x & 31;
    const int bh = w >> 8;
    const int q  = w & 255;
    const int h  = bh & 7;
    const unsigned FULL = 0xffffffffu;

    // ---- rotation coefficients ----
    float c0, s0, cp0, sp0, c1, s1, cp1, sp1;
    sincosf(theta[(h * 2 + 0) * 32 + lane], &s0, &c0);
    sincosf(theta[(h * 2 + 1) * 32 + lane], &s1, &c1);
    sincosf(phi[(h * 2 + 0) * 32 + lane], &sp0, &cp0);
    sincosf(phi[(h * 2 + 1) * 32 + lane], &sp1, &cp1);
    const float A0 = s0 * cp0, B0 = s0 * sp0;
    const float A1 = s1 * cp1, B1 = s1 * sp1;
    const int lm = (lane + 31) & 31;
    const int lp = (lane + 1) & 31;
    const float c1m = __shfl_sync(FULL, c1, lm);
    const float A1m = __shfl_sync(FULL, A1, lm);
    const float B1m = __shfl_sync(FULL, B1, lm);
    // packed f32x2 coefficient pairs
    const unsigned long long C0p  = pk2(c0, c0);
    const unsigned long long Am0p = pk2(-A0, -A0);
    const unsigned long long Ap0p = pk2( A0,  A0);
    const unsigned long long Bp0p = pk2( B0, -B0);
    const unsigned long long C1p  = pk2(c1, c1);
    const unsigned long long Am1p = pk2(-A1, -A1);
    const unsigned long long Bp1p = pk2( B1, -B1);
    const unsigned long long C1mp = pk2(c1m, c1m);
    const unsigned long long Ap1mp= pk2( A1m,  A1m);
    const unsigned long long Bp1mp= pk2( B1m, -B1m);
    // modrelu: scale = max(1 + (b-1e-5)*rcp(m+1e-5), 0)
    const float e0 = rbias[h * 64 + 2 * lane]     - 1e-5f;
    const float e1 = rbias[h * 64 + 2 * lane + 1] - 1e-5f;

    // ---- in-register softmax of this row ----
    const float* row = &g_attn[(bh * LL + q) * LL];
    float x[8];
    float mx = -__int_as_float(0x7f800000);
    #pragma unroll
    for (int j = 0; j < 8; ++j) { x[j] = row[lane + 32 * j]; mx = fmaxf(mx, x[j]); }
    #pragma unroll
    for (int off = 16; off > 0; off >>= 1) mx = fmaxf(mx, __shfl_xor_sync(FULL, mx, off));
    float s = 0.0f;
    #pragma unroll
    for (int j = 0; j < 8; ++j) { x[j] = __expf(x[j] - mx); s += x[j]; }
    #pragma unroll
    for (int off = 16; off > 0; off >>= 1) s += __shfl_xor_sync(FULL, s, off);
    float inv = 1.0f / s;
    #pragma unroll
    for (int j = 0; j < 8; ++j) x[j] *= inv;
    if (attn_out) {
        float* ao = &attn_out[(bh * LL + q) * LL];
        #pragma unroll
        for (int j = 0; j < 8; ++j) ao[lane + 32 * j] = x[j];
    }

    // ---- sequential scan with depth-3 u prefetch ring ----
    const float4* ub_lane = (const float4*)&g_u[bh * LL * DQ] + lane;
    float4 ring[4];
    ring[0] = ub_lane[0];
    ring[1] = ub_lane[32];
    ring[2] = ub_lane[64];
    ring[3] = ub_lane[64];   // dummy; overwritten at t=0

    float h0r = 0.f, h0i = 0.f, h1r = 0.f, h1i = 0.f;

    for (int chunk = 0; chunk < 8; ++chunk) {
        float xa = x[chunk];
        #pragma unroll 4
        for (int tt = 0; tt < 32; ++tt) {
            const int t = chunk * 32 + tt;
            float a = __shfl_sync(FULL, xa, tt);
            // prefetch t+3 into slot (t+3)&3 (holds consumed t-1)
            ring[(tt + 3) & 3] = ub_lane[(t + 3) * 32];
            // --- layer 0 (packed f32x2) ---
            float nar, nai, nbr, nbi;
            rot2(nar, nai, C0p, Am0p, Bp0p, h0r, h0i, h1r, h1i);
            rot2(nbr, nbi, C0p, Ap0p, Bp0p, h1r, h1i, h0r, h0i);
            h0r = nar; h0i = nai; h1r = nbr; h1i = nbi;
            // --- layer 1: parallel shuffles on layer-0 state ---
            {
                float h0pr = __shfl_sync(FULL, h0r, lp);
                float h0pi = __shfl_sync(FULL, h0i, lp);
                float h1mr = __shfl_sync(FULL, h1r, lm);
                float h1mi = __shfl_sync(FULL, h1i, lm);
                float nh1r, nh1i, nh0r, nh0i;
                rot2(nh1r, nh1i, C1p,  Am1p,  Bp1p,  h1r, h1i, h0pr, h0pi);
                rot2(nh0r, nh0i, C1mp, Ap1mp, Bp1mp, h0r, h0i, h1mr, h1mi);
                h0r = nh0r; h0i = nh0i; h1r = nh1r; h1i = nh1i;
            }
            // --- + a * u ---
            float4 u4 = ring[tt & 3];
            h0r = fmaf(a, u4.x, h0r); h0i = fmaf(a, u4.y, h0i);
            h1r = fmaf(a, u4.z, h1r); h1i = fmaf(a, u4.w, h1i);
            // --- modrelu: sc = max(1 + e*rcp(m+1e-5), 0) ---
            {
                float m2_0 = fmaf(h0r, h0r, h0i * h0i);
                float m2_1 = fmaf(h1r, h1r, h1i * h1i);
                float m0, m1, r0, r1;
                asm("sqrt.approx.f32 %0, %1;" : "=f"(m0) : "f"(m2_0));
                asm("sqrt.approx.f32 %0, %1;" : "=f"(m1) : "f"(m2_1));
                asm("rcp.approx.f32 %0, %1;" : "=f"(r0) : "f"(m0 + 1e-5f));
                asm("rcp.approx.f32 %0, %1;" : "=f"(r1) : "f"(m1 + 1e-5f));
                float sc0 = fmaxf(fmaf(e0, r0, 1.0f), 0.0f);
                float sc1 = fmaxf(fmaf(e1, r1, 1.0f), 0.0f);
                h0r *= sc0; h0i *= sc0;
                h1r *= sc1; h1i *= sc1;
            }
        }
    }
    const int b = bh >> 3;
    float* dst = &g_rnn[(b * LL + q) * DM + h * DQ];
    dst[2 * lane]     = h0r;
    dst[2 * lane + 1] = h1r;
}

// ---------------- launch ----------------
extern "C" void kernel_launch(void* const* d_in, const int* in_sizes, int n_in,
                              void* d_out, int out_size)
{
    const float* x_q    = (const float*)d_in[0];
    const float* x_k    = (const float*)d_in[1];
    const float* x_v    = (const float*)d_in[2];
    const float* maskp  = (const float*)d_in[3];
    const float* Wq     = (const float*)d_in[4];
    const float* bq     = (const float*)d_in[5];
    const float* Wk     = (const float*)d_in[6];
    const float* bk     = (const float*)d_in[7];
    const float* Wv     = (const float*)d_in[8];
    const float* bv     = (const float*)d_in[9];
    const float* Wo     = (const float*)d_in[10];
    const float* bo     = (const float*)d_in[11];
    const float* theta  = (const float*)d_in[12];
    const float* phi    = (const float*)d_in[13];
    const float* Win_re = (const float*)d_in[14];
    const float* Win_im = (const float*)d_in[15];
    const float* rbias  = (const float*)d_in[16];

    float* out = (float*)d_out;
    const int OUT_ELEMS  = BB * LL * DM;          // 262144
    const int ATTN_ELEMS = BB * NH * LL * LL;     // 1048576
    float* attn_out = (out_size >= OUT_ELEMS + ATTN_ELEMS) ? (out + OUT_ELEMS) : nullptr;

    qkv_gemm<<<dim3(8, 8, 3), 256>>>(x_q, x_k, x_v, Wq, Wk, Wv, bq, bk, bv);

    mid_kernel<<<384, 256>>>(maskp, Win_re, Win_im);

    rnn_kernel<<<512, 256>>>(theta, phi, rbias, attn_out);

    out_gemm_splitk<<<dim3(8, 8, 4), 256>>>(Wo);
    out_reduce<<<256, 256>>>(bo, out);
}

// round 16
// speedup vs baseline: 1.0413x; 1.0370x over previous
#include <cuda_runtime.h>
#include <math.h>

#define BB 2
#define LL 256
#define NH 8
#define DQ 64
#define DM 512

// ---------------- scratch (no allocation allowed) ----------------
__device__ float  g_q[BB*NH*LL*DQ];
__device__ float  g_k[BB*NH*LL*DQ];
__device__ float  g_v[BB*NH*LL*DQ];
__device__ float  g_attn[BB*NH*LL*LL];        // raw logits (softmax fused into rnn)
__device__ float2 g_u[BB*NH*LL*DQ + 512];     // +pad for prefetch overrun
__device__ float  g_rnn[BB*LL*DM];
__device__ float  g_part[4][BB*LL*DM];        // split-K partials for out gemm

// ---------------- f32x2 helpers ----------------
__device__ __forceinline__ unsigned long long pk2(float lo, float hi) {
    unsigned long long r;
    asm("mov.b64 %0, {%1, %2};" : "=l"(r) : "f"(lo), "f"(hi));
    return r;
}
// out = C (x) {hr,hi} + Am (x) {or_,oi} + Bp (x) {oi,or_}   (elementwise f32x2)
__device__ __forceinline__ void rot2(float& outr, float& outi,
    unsigned long long C, unsigned long long Am, unsigned long long Bp,
    float hr, float hi, float or_, float oi)
{
    asm("{\n\t"
        ".reg .b64 H, O, Os, T, R;\n\t"
        "mov.b64 H,  {%2, %3};\n\t"
        "mov.b64 O,  {%4, %5};\n\t"
        "mov.b64 Os, {%5, %4};\n\t"
        "mul.rn.f32x2 T, %8, Os;\n\t"
        "fma.rn.f32x2 T, %7, O, T;\n\t"
        "fma.rn.f32x2 R, %6, H, T;\n\t"
        "mov.b64 {%0, %1}, R;\n\t"
        "}" : "=f"(outr), "=f"(outi)
            : "f"(hr), "f"(hi), "f"(or_), "f"(oi),
              "l"(C), "l"(Am), "l"(Bp));
}

// ================= double-buffered GEMM body (generic tile, 256 threads) =================
struct GemmAcc { float v[4][4]; };

__device__ __forceinline__ void gemm_core_ks(
    const float* __restrict__ X, const float* __restrict__ W,
    float As[2][16][64], float Bs[2][16][64],
    int row0, int col0, int k_base, int nstage, int tid, GemmAcc& acc)
{
    const int tx = tid & 15, ty = tid >> 4;
    const int m  = tid >> 2,  kk = (tid & 3) * 4;
    const int kr = tid >> 4,  nn = (tid & 15) * 4;

    {
        float4 av = *(const float4*)&X[(row0 + m) * 512 + k_base + kk];
        As[0][kk+0][m] = av.x; As[0][kk+1][m] = av.y; As[0][kk+2][m] = av.z; As[0][kk+3][m] = av.w;
        *(float4*)&Bs[0][kr][nn] = *(const float4*)&W[(k_base + kr) * 512 + col0 + nn];
    }
    __syncthreads();

    for (int s = 0; s < nstage; ++s) {
        const int cur = s & 1;
        float4 av, bv;
        if (s < nstage - 1) {
            const int k0 = k_base + (s + 1) * 16;
            av = *(const float4*)&X[(row0 + m) * 512 + k0 + kk];
            bv = *(const float4*)&W[(k0 + kr) * 512 + col0 + nn];
        }
        #pragma unroll
        for (int k = 0; k < 16; ++k) {
            float4 a4 = *(const float4*)&As[cur][k][ty * 4];
            float4 b4 = *(const float4*)&Bs[cur][k][tx * 4];
            float a[4] = {a4.x, a4.y, a4.z, a4.w};
            float b[4] = {b4.x, b4.y, b4.z, b4.w};
            #pragma unroll
            for (int i = 0; i < 4; ++i)
                #pragma unroll
                for (int j = 0; j < 4; ++j)
                    acc.v[i][j] = fmaf(a[i], b[j], acc.v[i][j]);
        }
        if (s < nstage - 1) {
            const int nxt = cur ^ 1;
            As[nxt][kk+0][m] = av.x; As[nxt][kk+1][m] = av.y;
            As[nxt][kk+2][m] = av.z; As[nxt][kk+3][m] = av.w;
            *(float4*)&Bs[nxt][kr][nn] = bv;
        }
        __syncthreads();
    }
}

// -------- 64(M)x32(N) variant for qkv: 256 threads, 4x2 microtile, better grid balance -----
struct GemmAcc2 { float v[4][2]; };

__device__ __forceinline__ void gemm_core_n32(
    const float* __restrict__ X, const float* __restrict__ W,
    float As[2][16][64], float Bs[2][16][32],
    int row0, int col0, int tid, GemmAcc2& acc)
{
    const int tx = tid & 15, ty = tid >> 4;             // tx: 16 cols of 2, ty: 16 rows of 4
    const int m  = tid >> 2,  kk = (tid & 3) * 4;       // A loader (same as 64-wide)
    const int kr = tid >> 3,  nn = (tid & 7) * 4;       // B loader: 32 rows? no: kr 0..31 -> use tid>>3? 16 k-rows x 8 cols of 4
    // B tile is 16(k) x 32(n): 128 float4 loads -> first 128 threads
    const int bkr = tid >> 3;        // 0..31 (only tid<128 valid rows 0..15)
    const int bnn = (tid & 7) * 4;   // 0..28

    {
        float4 av = *(const float4*)&X[(row0 + m) * 512 + kk];
        As[0][kk+0][m] = av.x; As[0][kk+1][m] = av.y; As[0][kk+2][m] = av.z; As[0][kk+3][m] = av.w;
        if (tid < 128)
            *(float4*)&Bs[0][bkr][bnn] = *(const float4*)&W[bkr * 512 + col0 + bnn];
    }
    __syncthreads();

    for (int s = 0; s < 32; ++s) {
        const int cur = s & 1;
        float4 av, bv;
        if (s < 31) {
            const int k0 = (s + 1) * 16;
            av = *(const float4*)&X[(row0 + m) * 512 + k0 + kk];
            if (tid < 128)
                bv = *(const float4*)&W[(k0 + bkr) * 512 + col0 + bnn];
        }
        #pragma unroll
        for (int k = 0; k < 16; ++k) {
            float4 a4 = *(const float4*)&As[cur][k][ty * 4];
            float2 b2 = *(const float2*)&Bs[cur][k][tx * 2];
            float a[4] = {a4.x, a4.y, a4.z, a4.w};
            #pragma unroll
            for (int i = 0; i < 4; ++i) {
                acc.v[i][0] = fmaf(a[i], b2.x, acc.v[i][0]);
                acc.v[i][1] = fmaf(a[i], b2.y, acc.v[i][1]);
            }
        }
        if (s < 31) {
            const int nxt = cur ^ 1;
            As[nxt][kk+0][m] = av.x; As[nxt][kk+1][m] = av.y;
            As[nxt][kk+2][m] = av.z; As[nxt][kk+3][m] = av.w;
            if (tid < 128)
                *(float4*)&Bs[nxt][bkr][bnn] = bv;
        }
        __syncthreads();
    }
    (void)kr; (void)nn;
}

// ================= fused QKV GEMM: grid (8,16,3), 64x32 tiles =================
__global__ __launch_bounds__(256) void qkv_gemm(
    const float* __restrict__ xq, const float* __restrict__ xk, const float* __restrict__ xv,
    const float* __restrict__ Wq, const float* __restrict__ Wk, const float* __restrict__ Wv,
    const float* __restrict__ bq, const float* __restrict__ bk, const float* __restrict__ bv)
{
    __shared__ float As[2][16][64];
    __shared__ float Bs[2][16][32];
    const int z = blockIdx.z;
    const float* X    = (z == 0) ? xq : (z == 1) ? xk : xv;
    const float* W    = (z == 0) ? Wq : (z == 1) ? Wk : Wv;
    const float* bias = (z == 0) ? bq : (z == 1) ? bk : bv;
    float* Out        = (z == 0) ? g_q : (z == 1) ? g_k : g_v;

    const int tid = threadIdx.x;
    const int tx = tid & 15, ty = tid >> 4;
    const int row0 = blockIdx.x * 64, col0 = blockIdx.y * 32;
    GemmAcc2 acc = {};
    gemm_core_n32(X, W, As, Bs, row0, col0, tid, acc);

    #pragma unroll
    for (int i = 0; i < 4; ++i) {
        int mm = row0 + ty * 4 + i;
        #pragma unroll
        for (int j = 0; j < 2; ++j) {
            int n = col0 + tx * 2 + j;
            float val = acc.v[i][j] + bias[n];
            int b = mm >> 8, l = mm & 255, h = n >> 6, d = n & 63;
            Out[(((b * NH + h) << 8) + l) * DQ + d] = val;
        }
    }
}

// ================= out GEMM split-K=4: partial[z] over k in [z*128,(z+1)*128) =================
__global__ __launch_bounds__(256) void out_gemm_splitk(const float* __restrict__ W)
{
    __shared__ float As[2][16][64];
    __shared__ float Bs[2][16][64];
    const int tid = threadIdx.x;
    const int tx = tid & 15, ty = tid >> 4;
    const int row0 = blockIdx.x * 64, col0 = blockIdx.y * 64;
    const int z = blockIdx.z;
    GemmAcc acc = {};
    gemm_core_ks(g_rnn, W, As, Bs, row0, col0, z * 128, 8, tid, acc);

    float* dst = g_part[z];
    #pragma unroll
    for (int i = 0; i < 4; ++i) {
        int mm = row0 + ty * 4 + i;
        #pragma unroll
        for (int j = 0; j < 4; ++j) {
            int n = col0 + tx * 4 + j;
            dst[mm * 512 + n] = acc.v[i][j];
        }
    }
}

// ================= reduce: out = sum(part) + bias =================
__global__ __launch_bounds__(256) void out_reduce(
    const float* __restrict__ bias, float* __restrict__ Out)
{
    const int gidx = blockIdx.x * 256 + threadIdx.x;   // float4 index, 0..65535
    float4 p0 = ((const float4*)g_part[0])[gidx];
    float4 p1 = ((const float4*)g_part[1])[gidx];
    float4 p2 = ((const float4*)g_part[2])[gidx];
    float4 p3 = ((const float4*)g_part[3])[gidx];
    float4 b4 = ((const float4*)bias)[gidx & 127];
    float4 r;
    r.x = (p0.x + p1.x) + (p2.x + p3.x) + b4.x;
    r.y = (p0.y + p1.y) + (p2.y + p3.y) + b4.y;
    r.z = (p0.z + p1.z) + (p2.z + p3.z) + b4.z;
    r.w = (p0.w + p1.w) + (p2.w + p3.w) + b4.w;
    ((float4*)Out)[gidx] = r;
}

// ================= merged logits + u kernel =================
__global__ __launch_bounds__(256) void mid_kernel(
    const float* __restrict__ mask,
    const float* __restrict__ Wre, const float* __restrict__ Wim)
{
    __shared__ float sh[10240];
    const int bid = blockIdx.x;
    const int tid = threadIdx.x;

    if (bid < 256) {
        float* Qs = sh;
        float* Ks = sh + 64 * 65;
        const int q0 = (bid & 3) * 64, t0 = ((bid >> 2) & 3) * 64, bh = bid >> 4;
        const int b = bh >> 3;
        {
            const float* qsrc = &g_q[(bh * LL + q0) * DQ];
            const float* ksrc = &g_k[(bh * LL + t0) * DQ];
            #pragma unroll
            for (int i = 0; i < 4; ++i) {
                int idx = tid + 256 * i;
                int r = idx >> 4;
                int c = (idx & 15) * 4;
                float4 v = *(const float4*)&qsrc[r * 64 + c];
                Qs[r*65+c] = v.x; Qs[r*65+c+1] = v.y; Qs[r*65+c+2] = v.z; Qs[r*65+c+3] = v.w;
                float4 w = *(const float4*)&ksrc[r * 64 + c];
                Ks[r*65+c] = w.x; Ks[r*65+c+1] = w.y; Ks[r*65+c+2] = w.z; Ks[r*65+c+3] = w.w;
            }
        }
        __syncthreads();
        const int tx = tid & 15, ty = tid >> 4;
        float acc[4][4] = {};
        #pragma unroll 8
        for (int d = 0; d < 64; ++d) {
            float a[4], bb[4];
            #pragma unroll
            for (int i = 0; i < 4; ++i) a[i]  = Qs[(ty * 4 + i)*65 + d];
            #pragma unroll
            for (int j = 0; j < 4; ++j) bb[j] = Ks[(tx * 4 + j)*65 + d];
            #pragma unroll
            for (int i = 0; i < 4; ++i)
                #pragma unroll
                for (int j = 0; j < 4; ++j)
                    acc[i][j] = fmaf(a[i], bb[j], acc[i][j]);
        }
        const float NEG_INF = -__int_as_float(0x7f800000);
        #pragma unroll
        for (int i = 0; i < 4; ++i) {
            int q = q0 + ty * 4 + i;
            #pragma unroll
            for (int j = 0; j < 4; ++j) {
                int t = t0 + tx * 4 + j;
                float v = acc[i][j] * 0.125f;
                float mval = mask[b * LL * LL + q * LL + t];
                v = (mval == 1.0f) ? NEG_INF : v - mval;
                g_attn[(bh * LL + q) * LL + t] = v;
            }
        }
    } else {
        float* Vs = sh;
        float* Wr = sh + 2048;
        float* Wi = sh + 6144;
        const int b2 = bid - 256;
        const int bh = b2 & 15;
        const int rb = b2 >> 4;
        const int h  = bh & 7;
        {
            const float4* vsrc = (const float4*)&g_v[(bh * LL + rb * 32) * DQ];
            float4* vdst = (float4*)Vs;
            vdst[tid]       = vsrc[tid];
            vdst[tid + 256] = vsrc[tid + 256];
            const float4* wr = (const float4*)&Wre[h * 4096];
            const float4* wi = (const float4*)&Wim[h * 4096];
            float4* wrd = (float4*)Wr;
            float4* wid = (float4*)Wi;
            #pragma unroll
            for (int i = 0; i < 4; ++i) {
                wrd[tid + 256 * i] = wr[tid + 256 * i];
                wid[tid + 256 * i] = wi[tid + 256 * i];
            }
        }
        __syncthreads();
        const int tx = tid & 15, ty = tid >> 4;
        float ar[2][4] = {}, ai[2][4] = {};
        #pragma unroll 8
        for (int d = 0; d < 64; ++d) {
            float a0 = Vs[(ty * 2 + 0)*64 + d];
            float a1 = Vs[(ty * 2 + 1)*64 + d];
            float4 wr4 = *(const float4*)&Wr[d*64 + tx * 4];
            float4 wi4 = *(const float4*)&Wi[d*64 + tx * 4];
            float wrv[4] = {wr4.x, wr4.y, wr4.z, wr4.w};
            float wiv[4] = {wi4.x, wi4.y, wi4.z, wi4.w};
            #pragma unroll
            for (int j = 0; j < 4; ++j) {
                ar[0][j] = fmaf(a0, wrv[j], ar[0][j]);
                ai[0][j] = fmaf(a0, wiv[j], ai[0][j]);
                ar[1][j] = fmaf(a1, wrv[j], ar[1][j]);
                ai[1][j] = fmaf(a1, wiv[j], ai[1][j]);
            }
        }
        #pragma unroll
        for (int i = 0; i < 2; ++i) {
            int t = rb * 32 + ty * 2 + i;
            #pragma unroll
            for (int j = 0; j < 4; ++j) {
                int e = tx * 4 + j;
                g_u[(bh * LL + t) * DQ + e] = make_float2(ar[i][j], ai[i][j]);
            }
        }
    }
}

// ================= fused softmax + EUNN scan: one warp per (b,h,q) chain =================
// 128-thread blocks, grid 1024: ~6.92 blocks/SM -> near-perfect SM load balance
// (vs 512x256: 68 SMs @ 4 blocks / 80 SMs @ 3 -> 15% makespan imbalance).
__global__ __launch_bounds__(128, 8) void rnn_kernel(
    const float* __restrict__ theta, const float* __restrict__ phi,
    const float* __restrict__ rbias, float* __restrict__ attn_out)
{
    const int w = (blockIdx.x * blockDim.x + threadIdx.x) >> 5;  // 0..4095
    const int lane = threadIdx.x & 31;
    const int bh = w >> 8;
    const int q  = w & 255;
    const int h  = bh & 7;
    const unsigned FULL = 0xffffffffu;

    // ---- rotation coefficients ----
    float c0, s0, cp0, sp0, c1, s1, cp1, sp1;
    sincosf(theta[(h * 2 + 0) * 32 + lane], &s0, &c0);
    sincosf(theta[(h * 2 + 1) * 32 + lane], &s1, &c1);
    sincosf(phi[(h * 2 + 0) * 32 + lane], &sp0, &cp0);
    sincosf(phi[(h * 2 + 1) * 32 + lane], &sp1, &cp1);
    const float A0 = s0 * cp0, B0 = s0 * sp0;
    const float A1 = s1 * cp1, B1 = s1 * sp1;
    const int lm = (lane + 31) & 31;
    const int lp = (lane + 1) & 31;
    const float c1m = __shfl_sync(FULL, c1, lm);
    const float A1m = __shfl_sync(FULL, A1, lm);
    const float B1m = __shfl_sync(FULL, B1, lm);
    // packed f32x2 coefficient pairs
    const unsigned long long C0p  = pk2(c0, c0);
    const unsigned long long Am0p = pk2(-A0, -A0);
    const unsigned long long Ap0p = pk2( A0,  A0);
    const unsigned long long Bp0p = pk2( B0, -B0);
    const unsigned long long C1p  = pk2(c1, c1);
    const unsigned long long Am1p = pk2(-A1, -A1);
    const unsigned long long Bp1p = pk2( B1, -B1);
    const unsigned long long C1mp = pk2(c1m, c1m);
    const unsigned long long Ap1mp= pk2( A1m,  A1m);
    const unsigned long long Bp1mp= pk2( B1m, -B1m);
    // modrelu: scale = max(1 + (b-1e-5)*rcp(m+1e-5), 0)
    const float e0 = rbias[h * 64 + 2 * lane]     - 1e-5f;
    const float e1 = rbias[h * 64 + 2 * lane + 1] - 1e-5f;

    // ---- in-register softmax of this row ----
    const float* row = &g_attn[(bh * LL + q) * LL];
    float x[8];
    float mx = -__int_as_float(0x7f800000);
    #pragma unroll
    for (int j = 0; j < 8; ++j) { x[j] = row[lane + 32 * j]; mx = fmaxf(mx, x[j]); }
    #pragma unroll
    for (int off = 16; off > 0; off >>= 1) mx = fmaxf(mx, __shfl_xor_sync(FULL, mx, off));
    float s = 0.0f;
    #pragma unroll
    for (int j = 0; j < 8; ++j) { x[j] = __expf(x[j] - mx); s += x[j]; }
    #pragma unroll
    for (int off = 16; off > 0; off >>= 1) s += __shfl_xor_sync(FULL, s, off);
    float inv = 1.0f / s;
    #pragma unroll
    for (int j = 0; j < 8; ++j) x[j] *= inv;
    if (attn_out) {
        float* ao = &attn_out[(bh * LL + q) * LL];
        #pragma unroll
        for (int j = 0; j < 8; ++j) ao[lane + 32 * j] = x[j];
    }

    // ---- sequential scan with depth-3 u prefetch ring ----
    const float4* ub_lane = (const float4*)&g_u[bh * LL * DQ] + lane;
    float4 ring[4];
    ring[0] = ub_lane[0];
    ring[1] = ub_lane[32];
    ring[2] = ub_lane[64];
    ring[3] = ub_lane[64];   // dummy; overwritten at t=0

    float h0r = 0.f, h0i = 0.f, h1r = 0.f, h1i = 0.f;

    for (int chunk = 0; chunk < 8; ++chunk) {
        float xa = x[chunk];
        #pragma unroll 4
        for (int tt = 0; tt < 32; ++tt) {
            const int t = chunk * 32 + tt;
            float a = __shfl_sync(FULL, xa, tt);
            // prefetch t+3 into slot (t+3)&3 (holds consumed t-1)
            ring[(tt + 3) & 3] = ub_lane[(t + 3) * 32];
            // --- layer 0 (packed f32x2) ---
            float nar, nai, nbr, nbi;
            rot2(nar, nai, C0p, Am0p, Bp0p, h0r, h0i, h1r, h1i);
            rot2(nbr, nbi, C0p, Ap0p, Bp0p, h1r, h1i, h0r, h0i);
            h0r = nar; h0i = nai; h1r = nbr; h1i = nbi;
            // --- layer 1: parallel shuffles on layer-0 state ---
            {
                float h0pr = __shfl_sync(FULL, h0r, lp);
                float h0pi = __shfl_sync(FULL, h0i, lp);
                float h1mr = __shfl_sync(FULL, h1r, lm);
                float h1mi = __shfl_sync(FULL, h1i, lm);
                float nh1r, nh1i, nh0r, nh0i;
                rot2(nh1r, nh1i, C1p,  Am1p,  Bp1p,  h1r, h1i, h0pr, h0pi);
                rot2(nh0r, nh0i, C1mp, Ap1mp, Bp1mp, h0r, h0i, h1mr, h1mi);
                h0r = nh0r; h0i = nh0i; h1r = nh1r; h1i = nh1i;
            }
            // --- + a * u ---
            float4 u4 = ring[tt & 3];
            h0r = fmaf(a, u4.x, h0r); h0i = fmaf(a, u4.y, h0i);
            h1r = fmaf(a, u4.z, h1r); h1i = fmaf(a, u4.w, h1i);
            // --- modrelu: sc = max(1 + e*rcp(m+1e-5), 0) ---
            {
                float m2_0 = fmaf(h0r, h0r, h0i * h0i);
                float m2_1 = fmaf(h1r, h1r, h1i * h1i);
                float m0, m1, r0, r1;
                asm("sqrt.approx.f32 %0, %1;" : "=f"(m0) : "f"(m2_0));
                asm("sqrt.approx.f32 %0, %1;" : "=f"(m1) : "f"(m2_1));
                asm("rcp.approx.f32 %0, %1;" : "=f"(r0) : "f"(m0 + 1e-5f));
                asm("rcp.approx.f32 %0, %1;" : "=f"(r1) : "f"(m1 + 1e-5f));
                float sc0 = fmaxf(fmaf(e0, r0, 1.0f), 0.0f);
                float sc1 = fmaxf(fmaf(e1, r1, 1.0f), 0.0f);
                h0r *= sc0; h0i *= sc0;
                h1r *= sc1; h1i *= sc1;
            }
        }
    }
    const int b = bh >> 3;
    float* dst = &g_rnn[(b * LL + q) * DM + h * DQ];
    dst[2 * lane]     = h0r;
    dst[2 * lane + 1] = h1r;
}

// ---------------- launch ----------------
extern "C" void kernel_launch(void* const* d_in, const int* in_sizes, int n_in,
                              void* d_out, int out_size)
{
    const float* x_q    = (const float*)d_in[0];
    const float* x_k    = (const float*)d_in[1];
    const float* x_v    = (const float*)d_in[2];
    const float* maskp  = (const float*)d_in[3];
    const float* Wq     = (const float*)d_in[4];
    const float* bq     = (const float*)d_in[5];
    const float* Wk     = (const float*)d_in[6];
    const float* bk     = (const float*)d_in[7];
    const float* Wv     = (const float*)d_in[8];
    const float* bv     = (const float*)d_in[9];
    const float* Wo     = (const float*)d_in[10];
    const float* bo     = (const float*)d_in[11];
    const float* theta  = (const float*)d_in[12];
    const float* phi    = (const float*)d_in[13];
    const float* Win_re = (const float*)d_in[14];
    const float* Win_im = (const float*)d_in[15];
    const float* rbias  = (const float*)d_in[16];

    float* out = (float*)d_out;
    const int OUT_ELEMS  = BB * LL * DM;          // 262144
    const int ATTN_ELEMS = BB * NH * LL * LL;     // 1048576
    float* attn_out = (out_size >= OUT_ELEMS + ATTN_ELEMS) ? (out + OUT_ELEMS) : nullptr;

    qkv_gemm<<<dim3(8, 16, 3), 256>>>(x_q, x_k, x_v, Wq, Wk, Wv, bq, bk, bv);

    mid_kernel<<<384, 256>>>(maskp, Win_re, Win_im);

    rnn_kernel<<<1024, 128>>>(theta, phi, rbias, attn_out);

    out_gemm_splitk<<<dim3(8, 8, 4), 256>>>(Wo);
    out_reduce<<<256, 256>>>(bo, out);
}